// round 4
// baseline (speedup 1.0000x reference)
#include <cuda_runtime.h>
#include <cuda_bf16.h>
#include <math.h>

// Fixed shapes: N = 12288
#define NPTS  12288
#define M     20          // cells per axis in warped (uniform) space
#define M3    (M * M * M) // 8000 cells
#define FINF  (3.0e38f)

// Device scratch (no allocations allowed)
__device__ float4 g_sorted[NPTS];     // cell-sorted points {x,y,z, bitcast(origIdx)}
__device__ int    g_hist[M3];
__device__ int    g_cursor[M3];
__device__ int    g_cellStart[M3 + 1];
__device__ int    g_cellOf[NPTS];

// Monotone bin function: gaussian CDF warp -> uniform cube -> fixed grid.
// MUST be identical everywhere it's used (binning and query bounds).
__device__ __forceinline__ int binf(float x) {
    float F = 0.5f * erfcf(-x * 0.7071067811865475f);   // Phi(x) in (0,1)
    int c = (int)(F * (float)M);
    return min(max(c, 0), M - 1);
}

// ---- K1: clear histogram -------------------------------------------------
__global__ void clear_kernel() {
    int i = blockIdx.x * blockDim.x + threadIdx.x;
    if (i < M3) g_hist[i] = 0;
}

// ---- K2: bin points ------------------------------------------------------
__global__ void bin_kernel(const float* __restrict__ pts) {
    int i = blockIdx.x * blockDim.x + threadIdx.x;
    if (i >= NPTS) return;
    float x = pts[3 * i + 0], y = pts[3 * i + 1], z = pts[3 * i + 2];
    int c = (binf(z) * M + binf(y)) * M + binf(x);
    g_cellOf[i] = c;
    atomicAdd(&g_hist[c], 1);
}

// ---- K3: exclusive scan over 8000 cells (single block) -------------------
#define SCAN_T 1024
#define SCAN_C 8          // cells per thread (8192 >= M3)
__global__ __launch_bounds__(SCAN_T)
void scan_kernel() {
    __shared__ int sh[SCAN_T];
    int tid = threadIdx.x;
    int base = tid * SCAN_C;
    int v[SCAN_C];
    int sum = 0;
    #pragma unroll
    for (int k = 0; k < SCAN_C; ++k) {
        int c = base + k;
        int h = (c < M3) ? g_hist[c] : 0;
        v[k] = sum;            // exclusive within chunk
        sum += h;
    }
    sh[tid] = sum;
    __syncthreads();
    // Hillis-Steele inclusive scan over 1024 chunk sums
    for (int off = 1; off < SCAN_T; off <<= 1) {
        int t = (tid >= off) ? sh[tid - off] : 0;
        __syncthreads();
        sh[tid] += t;
        __syncthreads();
    }
    int pre = sh[tid] - sum;   // exclusive chunk offset
    #pragma unroll
    for (int k = 0; k < SCAN_C; ++k) {
        int c = base + k;
        if (c < M3) {
            int st = pre + v[k];
            g_cellStart[c] = st;
            g_cursor[c]    = st;
        }
    }
    if (tid == 0) g_cellStart[M3] = NPTS;
}

// ---- K4: scatter into cell-sorted order ----------------------------------
__global__ void scatter_kernel(const float* __restrict__ pts) {
    int i = blockIdx.x * blockDim.x + threadIdx.x;
    if (i >= NPTS) return;
    int c = g_cellOf[i];
    int pos = atomicAdd(&g_cursor[c], 1);
    g_sorted[pos] = make_float4(pts[3 * i + 0], pts[3 * i + 1], pts[3 * i + 2],
                                __int_as_float(i));
}

// ---- K5: exact 3-NN via warped-grid search + covariance ------------------
__global__ __launch_bounds__(64)
void nn_cov_kernel(const float* __restrict__ quat, float* __restrict__ out) {
    int k = blockIdx.x * blockDim.x + threadIdx.x;
    if (k >= NPTS) return;

    float4 me = g_sorted[k];
    const float x = me.x, y = me.y, z = me.z;
    const int myi = __float_as_int(me.w);

    float m1 = FINF, m2 = FINF, m3 = FINF;   // smallest three d^2, ascending
    int found = 0;

    // Scan a cell range, skipping cells inside the already-scanned box.
    auto scanBox = [&](int lx0, int hx0, int ly0, int hy0, int lz0, int hz0,
                       int sx0, int sx1, int sy0, int sy1, int sz0, int sz1) {
        for (int zz = lz0; zz <= hz0; ++zz)
            for (int yy = ly0; yy <= hy0; ++yy)
                for (int xx = lx0; xx <= hx0; ++xx) {
                    if (xx >= sx0 && xx <= sx1 && yy >= sy0 && yy <= sy1 &&
                        zz >= sz0 && zz <= sz1) continue;
                    int c = (zz * M + yy) * M + xx;
                    int s = g_cellStart[c];
                    int e = g_cellStart[c + 1];
                    for (int t = s; t < e; ++t) {
                        float4 q = g_sorted[t];
                        if (__float_as_int(q.w) == myi) continue;
                        float dx = x - q.x, dy = y - q.y, dz = z - q.z;
                        float d2 = fmaf(dz, dz, fmaf(dy, dy, dx * dx));
                        float t1 = fmaxf(d2, m1); m1 = fminf(d2, m1);
                        float t2 = fmaxf(t1, m2); m2 = fminf(t1, m2);
                        m3 = fminf(t2, m3);
                        ++found;
                    }
                }
    };

    const int cx = binf(x), cy = binf(y), cz = binf(z);

    // Phase A: initial 3^3 cube (clamped). ~41 candidates expected.
    int lx = max(cx - 1, 0), hx = min(cx + 1, M - 1);
    int ly = max(cy - 1, 0), hy = min(cy + 1, M - 1);
    int lz = max(cz - 1, 0), hz = min(cz + 1, M - 1);
    scanBox(lx, hx, ly, hy, lz, hz, 1, -1, 1, -1, 1, -1);  // empty skip box

    // Phase B: expand until we have at least 3 neighbors (statistically never).
    while (found < 3) {
        int nlx = max(lx - 1, 0), nhx = min(hx + 1, M - 1);
        int nly = max(ly - 1, 0), nhy = min(hy + 1, M - 1);
        int nlz = max(lz - 1, 0), nhz = min(hz + 1, M - 1);
        if (nlx == lx && nhx == hx && nly == ly && nhy == hy &&
            nlz == lz && nhz == hz) break;                  // whole grid scanned
        scanBox(nlx, nhx, nly, nhy, nlz, nhz, lx, hx, ly, hy, lz, hz);
        lx = nlx; hx = nhx; ly = nly; hy = nhy; lz = nlz; hz = nhz;
    }

    // Phase C: exactness pass. Any point closer than d3 must lie in the
    // original-space box [x±d3]x[y±d3]x[z±d3]; map its bounds through the
    // same monotone bin function and scan uncovered cells. d3 only shrinks,
    // so one pass over this (conservative) range suffices.
    {
        float d3 = sqrtf(m3);
        int tlx = min(lx, binf(x - d3)), thx = max(hx, binf(x + d3));
        int tly = min(ly, binf(y - d3)), thy = max(hy, binf(y + d3));
        int tlz = min(lz, binf(z - d3)), thz = max(hz, binf(z + d3));
        scanBox(tlx, thx, tly, thy, tlz, thz, lx, hx, ly, hy, lz, hz);
    }

    // ---- scale + covariance ----
    float d1 = sqrtf(m1);
    float d2 = sqrtf(m2);
    float d3 = sqrtf(m3);
    float mean = (d1 + d2 + d3) * (1.0f / 3.0f);
    float s = 0.001f * fmaxf(mean, 1e-5f);

    float qr = quat[4 * myi + 0];
    float qx = quat[4 * myi + 1];
    float qy = quat[4 * myi + 2];
    float qz = quat[4 * myi + 3];
    float inv = rsqrtf(qr * qr + qx * qx + qy * qy + qz * qz);
    qr *= inv; qx *= inv; qy *= inv; qz *= inv;

    float R00 = 1.0f - 2.0f * (qy * qy + qz * qz);
    float R01 = 2.0f * (qx * qy - qr * qz);
    float R02 = 2.0f * (qx * qz + qr * qy);
    float R10 = 2.0f * (qx * qy + qr * qz);
    float R11 = 1.0f - 2.0f * (qx * qx + qz * qz);
    float R12 = 2.0f * (qy * qz - qr * qx);
    float R20 = 2.0f * (qx * qz - qr * qy);
    float R21 = 2.0f * (qy * qz + qr * qx);
    float R22 = 1.0f - 2.0f * (qx * qx + qy * qy);

    float M00 = s * R00, M01 = s * R01, M02 = s * R02;
    float M10 = s * R10, M11 = s * R11, M12 = s * R12;
    float M20 = s * R20, M21 = s * R21, M22 = s * R22;

    float c00 = M00 * M00 + M01 * M01 + M02 * M02;
    float c01 = M00 * M10 + M01 * M11 + M02 * M12;
    float c02 = M00 * M20 + M01 * M21 + M02 * M22;
    float c11 = M10 * M10 + M11 * M11 + M12 * M12;
    float c12 = M10 * M20 + M11 * M21 + M12 * M22;
    float c22 = M20 * M20 + M21 * M21 + M22 * M22;

    float* o = out + (size_t)myi * 9;
    o[0] = c00; o[1] = c01; o[2] = c02;
    o[3] = c01; o[4] = c11; o[5] = c12;
    o[6] = c02; o[7] = c12; o[8] = c22;
}

extern "C" void kernel_launch(void* const* d_in, const int* in_sizes, int n_in,
                              void* d_out, int out_size) {
    const float* pts  = (const float*)d_in[0];   // (N, 3) float32
    const float* quat = (const float*)d_in[1];   // (N, 4) float32
    float* out = (float*)d_out;                  // (N, 3, 3) float32

    clear_kernel  <<<(M3 + 255) / 256, 256>>>();
    bin_kernel    <<<(NPTS + 255) / 256, 256>>>(pts);
    scan_kernel   <<<1, SCAN_T>>>();
    scatter_kernel<<<(NPTS + 255) / 256, 256>>>(pts);
    nn_cov_kernel <<<NPTS / 64, 64>>>(quat, out);
}

// round 5
// speedup vs baseline: 1.7527x; 1.7527x over previous
#include <cuda_runtime.h>
#include <cuda_bf16.h>
#include <math.h>

// Fixed shapes: N = 12288
#define NPTS  12288
#define M     20          // cells per axis in warped (uniform) space
#define M3    (M * M * M) // 8000 cells
#define FINF  (3.0e38f)
#define FULLMASK 0xFFFFFFFFu

// Device scratch (no allocations allowed)
__device__ float4 g_sorted[NPTS];     // cell-sorted points {x,y,z, bitcast(origIdx)}
__device__ int    g_hist[M3];         // zero-initialized at load; scan re-zeroes each run
__device__ int    g_cursor[M3];
__device__ int    g_cellStart[M3 + 1];
__device__ int    g_cellOf[NPTS];

// Monotone bin function: gaussian CDF warp -> uniform cube -> fixed grid.
__device__ __forceinline__ int binf(float x) {
    float F = 0.5f * erfcf(-x * 0.7071067811865475f);   // Phi(x) in (0,1)
    int c = (int)(F * (float)M);
    return min(max(c, 0), M - 1);
}

// ascending insert of d into m1<=m2<=m3
__device__ __forceinline__ void ins3(float d, float& m1, float& m2, float& m3) {
    float t1 = fmaxf(d, m1);  m1 = fminf(d, m1);
    float t2 = fmaxf(t1, m2); m2 = fminf(t1, m2);
    m3 = fminf(t2, m3);
}

// merge two ascending sorted-3 lists, keep 3 smallest
__device__ __forceinline__ void merge3asc(float& m1, float& m2, float& m3,
                                          float s1, float s2, float s3) {
    float a = fminf(m1, s1), b = fmaxf(m1, s1);
    float c = fminf(m2, s2);
    float e = fminf(m3, s3);
    float t = fmaxf(b, c);
    m1 = a; m2 = fminf(b, c); m3 = fminf(t, e);
}

// ---- K1: bin points (g_hist must be zero on entry; scan re-zeroes) -------
__global__ void bin_kernel(const float* __restrict__ pts) {
    int i = blockIdx.x * blockDim.x + threadIdx.x;
    if (i >= NPTS) return;
    float x = pts[3 * i + 0], y = pts[3 * i + 1], z = pts[3 * i + 2];
    int c = (binf(z) * M + binf(y)) * M + binf(x);
    g_cellOf[i] = c;
    atomicAdd(&g_hist[c], 1);
}

// ---- K2: exclusive scan over 8000 cells (single block); zeroes g_hist ----
#define SCAN_T 1024
#define SCAN_C 8
__global__ __launch_bounds__(SCAN_T)
void scan_kernel() {
    __shared__ int sh[SCAN_T];
    int tid = threadIdx.x;
    int base = tid * SCAN_C;
    int v[SCAN_C];
    int sum = 0;
    #pragma unroll
    for (int k = 0; k < SCAN_C; ++k) {
        int c = base + k;
        int h = (c < M3) ? g_hist[c] : 0;
        if (c < M3) g_hist[c] = 0;         // restore invariant for next replay
        v[k] = sum;
        sum += h;
    }
    sh[tid] = sum;
    __syncthreads();
    for (int off = 1; off < SCAN_T; off <<= 1) {
        int t = (tid >= off) ? sh[tid - off] : 0;
        __syncthreads();
        sh[tid] += t;
        __syncthreads();
    }
    int pre = sh[tid] - sum;
    #pragma unroll
    for (int k = 0; k < SCAN_C; ++k) {
        int c = base + k;
        if (c < M3) {
            int st = pre + v[k];
            g_cellStart[c] = st;
            g_cursor[c]    = st;
        }
    }
    if (tid == 0) g_cellStart[M3] = NPTS;
}

// ---- K3: scatter into cell-sorted order ----------------------------------
__global__ void scatter_kernel(const float* __restrict__ pts) {
    int i = blockIdx.x * blockDim.x + threadIdx.x;
    if (i >= NPTS) return;
    int c = g_cellOf[i];
    int pos = atomicAdd(&g_cursor[c], 1);
    g_sorted[pos] = make_float4(pts[3 * i + 0], pts[3 * i + 1], pts[3 * i + 2],
                                __int_as_float(i));
}

// ---- K4: warp-per-point exact 3-NN + covariance --------------------------
__global__ __launch_bounds__(256)
void nn_cov_kernel(const float* __restrict__ quat, float* __restrict__ out) {
    const int w    = blockIdx.x * 8 + (threadIdx.x >> 5);   // point (sorted pos)
    const int lane = threadIdx.x & 31;

    const float4 me = g_sorted[w];
    const float x = me.x, y = me.y, z = me.z;
    const int myi = __float_as_int(me.w);

    const int cx = binf(x), cy = binf(y), cz = binf(z);
    int lx = max(cx - 1, 0), hx = min(cx + 1, M - 1);
    int ly = max(cy - 1, 0), hy = min(cy + 1, M - 1);
    int lz = max(cz - 1, 0), hz = min(cz + 1, M - 1);

    // ---- Phase A: flatten <=9 contiguous row-segments, lane-parallel ----
    const int wy = hy - ly + 1;
    const int nrows = (hz - lz + 1) * wy;
    int segS = 0, len = 0;
    if (lane < nrows) {
        int zz = lz + lane / wy;
        int yy = ly + lane % wy;
        int rowbase = (zz * M + yy) * M;
        segS = g_cellStart[rowbase + lx];
        len  = g_cellStart[rowbase + hx + 1] - segS;
    }
    // inclusive warp scan of len
    int pref = len;
    #pragma unroll
    for (int off = 1; off < 32; off <<= 1) {
        int t = __shfl_up_sync(FULLMASK, pref, off);
        if (lane >= off) pref += t;
    }
    const int T = __shfl_sync(FULLMASK, pref, 31);
    int pexcl = pref - len;                 // lanes >= nrows: pexcl == T

    // broadcast segment tables into registers
    int ps[9], bs[9];
    #pragma unroll
    for (int s = 0; s < 9; ++s) {
        ps[s] = __shfl_sync(FULLMASK, pexcl, s);
        bs[s] = __shfl_sync(FULLMASK, segS,  s);
    }

    float m1 = FINF, m2 = FINF, m3 = FINF;  // per-lane top-3 (ascending d^2)

    for (int base = 0; base < T; base += 32) {
        int idx = base + lane;
        int p = ps[0], b = bs[0];
        #pragma unroll
        for (int s = 1; s < 9; ++s) {
            bool g = (idx >= ps[s]);
            p = g ? ps[s] : p;
            b = g ? bs[s] : b;
        }
        int addr = b + (idx - p);
        if (idx < T && addr != w) {
            float4 q = g_sorted[addr];
            float dx = x - q.x, dy = y - q.y, dz = z - q.z;
            float d2 = fmaf(dz, dz, fmaf(dy, dy, dx * dx));
            ins3(d2, m1, m2, m3);
        }
    }

    // ---- Phase B (rare): not enough candidates -> full rescan ----
    if (T < 4) {
        m1 = m2 = m3 = FINF;
        for (int t = lane; t < NPTS; t += 32) {
            if (t == w) continue;
            float4 q = g_sorted[t];
            float dx = x - q.x, dy = y - q.y, dz = z - q.z;
            ins3(fmaf(dz, dz, fmaf(dy, dy, dx * dx)), m1, m2, m3);
        }
        lx = 0; hx = M - 1; ly = 0; hy = M - 1; lz = 0; hz = M - 1;
    }

    // mid-reduce (bound only; per-lane triples kept)
    float r1 = m1, r2 = m2, r3 = m3;
    #pragma unroll
    for (int off = 16; off >= 1; off >>= 1) {
        float s1 = __shfl_xor_sync(FULLMASK, r1, off);
        float s2 = __shfl_xor_sync(FULLMASK, r2, off);
        float s3 = __shfl_xor_sync(FULLMASK, r3, off);
        merge3asc(r1, r2, r3, s1, s2, s3);
    }

    // ---- Phase C: exactness pass over ball-box minus scanned box ----
    {
        float rad = sqrtf(r3) * 1.0001f;
        int nlx = min(lx, binf(x - rad)), nhx = max(hx, binf(x + rad));
        int nly = min(ly, binf(y - rad)), nhy = max(hy, binf(y + rad));
        int nlz = min(lz, binf(z - rad)), nhz = max(hz, binf(z + rad));
        bool covered = (nlx >= lx) && (nhx <= hx) && (nly >= ly) &&
                       (nhy <= hy) && (nlz >= lz) && (nhz <= hz);
        if (!covered) {
            for (int zz = nlz; zz <= nhz; ++zz) {
                for (int yy = nly; yy <= nhy; ++yy) {
                    int rowbase = (zz * M + yy) * M;
                    bool oldRow = (zz >= lz && zz <= hz && yy >= ly && yy <= hy);
                    // subrange 1: [nlx, oldRow ? lx-1 : nhx]
                    int a = nlx, bnd = oldRow ? lx - 1 : nhx;
                    for (int pass = 0; pass < 2; ++pass) {
                        if (a <= bnd) {
                            int s = g_cellStart[rowbase + a];
                            int e = g_cellStart[rowbase + bnd + 1];
                            for (int t = s + lane; t < e; t += 32) {
                                if (t == w) continue;
                                float4 q = g_sorted[t];
                                float dx = x - q.x, dy = y - q.y, dz = z - q.z;
                                ins3(fmaf(dz, dz, fmaf(dy, dy, dx * dx)), m1, m2, m3);
                            }
                        }
                        if (!oldRow) break;
                        a = hx + 1; bnd = nhx;   // subrange 2 for old rows
                    }
                }
            }
        }
    }

    // ---- final reduce ----
    #pragma unroll
    for (int off = 16; off >= 1; off >>= 1) {
        float s1 = __shfl_xor_sync(FULLMASK, m1, off);
        float s2 = __shfl_xor_sync(FULLMASK, m2, off);
        float s3 = __shfl_xor_sync(FULLMASK, m3, off);
        merge3asc(m1, m2, m3, s1, s2, s3);
    }

    if (lane != 0) return;

    // ---- scale + covariance (lane 0) ----
    float d1 = sqrtf(m1), d2s = sqrtf(m2), d3s = sqrtf(m3);
    float mean = (d1 + d2s + d3s) * (1.0f / 3.0f);
    float s = 0.001f * fmaxf(mean, 1e-5f);

    float qr = quat[4 * myi + 0];
    float qx = quat[4 * myi + 1];
    float qy = quat[4 * myi + 2];
    float qz = quat[4 * myi + 3];
    float inv = rsqrtf(qr * qr + qx * qx + qy * qy + qz * qz);
    qr *= inv; qx *= inv; qy *= inv; qz *= inv;

    float R00 = 1.0f - 2.0f * (qy * qy + qz * qz);
    float R01 = 2.0f * (qx * qy - qr * qz);
    float R02 = 2.0f * (qx * qz + qr * qy);
    float R10 = 2.0f * (qx * qy + qr * qz);
    float R11 = 1.0f - 2.0f * (qx * qx + qz * qz);
    float R12 = 2.0f * (qy * qz - qr * qx);
    float R20 = 2.0f * (qx * qz - qr * qy);
    float R21 = 2.0f * (qy * qz + qr * qx);
    float R22 = 1.0f - 2.0f * (qx * qx + qy * qy);

    float M00 = s * R00, M01 = s * R01, M02 = s * R02;
    float M10 = s * R10, M11 = s * R11, M12 = s * R12;
    float M20 = s * R20, M21 = s * R21, M22 = s * R22;

    float c00 = M00 * M00 + M01 * M01 + M02 * M02;
    float c01 = M00 * M10 + M01 * M11 + M02 * M12;
    float c02 = M00 * M20 + M01 * M21 + M02 * M22;
    float c11 = M10 * M10 + M11 * M11 + M12 * M12;
    float c12 = M10 * M20 + M11 * M21 + M12 * M22;
    float c22 = M20 * M20 + M21 * M21 + M22 * M22;

    float* o = out + (size_t)myi * 9;
    o[0] = c00; o[1] = c01; o[2] = c02;
    o[3] = c01; o[4] = c11; o[5] = c12;
    o[6] = c02; o[7] = c12; o[8] = c22;
}

extern "C" void kernel_launch(void* const* d_in, const int* in_sizes, int n_in,
                              void* d_out, int out_size) {
    const float* pts  = (const float*)d_in[0];   // (N, 3) float32
    const float* quat = (const float*)d_in[1];   // (N, 4) float32
    float* out = (float*)d_out;                  // (N, 3, 3) float32

    bin_kernel    <<<(NPTS + 255) / 256, 256>>>(pts);
    scan_kernel   <<<1, SCAN_T>>>();
    scatter_kernel<<<(NPTS + 255) / 256, 256>>>(pts);
    nn_cov_kernel <<<NPTS / 8, 256>>>(quat, out);
}